// round 1
// baseline (speedup 1.0000x reference)
#include <cuda_runtime.h>

// out[b,k] = (WHT_2048(concat(x1[b],x2[b]))[k])^2 / 2048
// (RZ phase is unit-modulus and input is real -> |.|^2 kills it; Hadamard
// stages = unnormalized WHT * 2^{-11/2}; squared -> 1/2048 scale.)

#define THREADS 128
#define GRP 17  // 16 floats per group + 1 pad float (bank-conflict avoidance)

__device__ __forceinline__ void wht16(float* v) {
#pragma unroll
    for (int m = 1; m < 16; m <<= 1) {
#pragma unroll
        for (int i = 0; i < 16; ++i) {
            if ((i & m) == 0) {
                float a = v[i];
                float b = v[i | m];
                v[i]     = a + b;
                v[i | m] = a - b;
            }
        }
    }
}

__global__ void __launch_bounds__(THREADS) qf_wht_kernel(
    const float* __restrict__ x1,
    const float* __restrict__ x2,
    float* __restrict__ out)
{
    __shared__ float buf0[THREADS * GRP];
    __shared__ float buf1[THREADS * GRP];

    const int t   = threadIdx.x;
    const int row = blockIdx.x;

    float v[16];

    // ---- Load: layout A, j = t*16 + i  (float4, fully coalesced) ----
    const float* src = (t < 64)
        ? (x1 + (size_t)row * 1024 + (size_t)t * 16)
        : (x2 + (size_t)row * 1024 + (size_t)(t - 64) * 16);
    const float4* p4 = reinterpret_cast<const float4*>(src);
#pragma unroll
    for (int k = 0; k < 4; ++k) {
        float4 f = p4[k];
        v[4 * k + 0] = f.x;
        v[4 * k + 1] = f.y;
        v[4 * k + 2] = f.z;
        v[4 * k + 3] = f.w;
    }

    // Stage bits 0..3 (i index of layout A)
    wht16(v);

    // store layout A: addr = t*GRP + i  (conflict-free)
#pragma unroll
    for (int i = 0; i < 16; ++i) buf0[t * GRP + i] = v[i];
    __syncthreads();

    // ---- Layout B: j = i*128 + t  (i = bits 7..10) ----
#pragma unroll
    for (int i = 0; i < 16; ++i) {
        int j = i * 128 + t;
        v[i] = buf0[(j >> 4) * GRP + (j & 15)];
    }

    // Stage bits 7..10
    wht16(v);

#pragma unroll
    for (int i = 0; i < 16; ++i) {
        int j = i * 128 + t;
        buf1[(j >> 4) * GRP + (j & 15)] = v[i];
    }
    __syncthreads();

    // ---- Layout C: j = (t&15) | ((i&7)<<4) | ((t>>4)<<7) | ((i>>3)<<10) ----
    const int base = (t & 15) | ((t >> 4) << 7);
#pragma unroll
    for (int i = 0; i < 16; ++i) {
        int j = base | ((i & 7) << 4) | ((i >> 3) << 10);
        v[i] = buf1[(j >> 4) * GRP + (j & 15)];
    }

    // Stage bits 4..6: WHT8 on each half (halves differ only in bit 10, already done)
#pragma unroll
    for (int m = 1; m < 8; m <<= 1) {
#pragma unroll
        for (int h = 0; h < 16; h += 8) {
#pragma unroll
            for (int i = 0; i < 8; ++i) {
                if ((i & m) == 0) {
                    float a = v[h + i];
                    float b = v[h + (i | m)];
                    v[h + i]       = a + b;
                    v[h + (i | m)] = a - b;
                }
            }
        }
    }

    // ---- Epilogue: |.|^2 / 2048, store ----
    const float scale = 1.0f / 2048.0f;
    float* orow = out + (size_t)row * 2048;
#pragma unroll
    for (int i = 0; i < 16; ++i) {
        int j = base | ((i & 7) << 4) | ((i >> 3) << 10);
        orow[j] = v[i] * v[i] * scale;
    }
}

extern "C" void kernel_launch(void* const* d_in, const int* in_sizes, int n_in,
                              void* d_out, int out_size)
{
    const float* x1 = (const float*)d_in[0];
    const float* x2 = (const float*)d_in[1];
    float* out = (float*)d_out;
    (void)in_sizes; (void)n_in; (void)out_size;

    qf_wht_kernel<<<8192, THREADS>>>(x1, x2, out);
}

// round 2
// speedup vs baseline: 1.0948x; 1.0948x over previous
#include <cuda_runtime.h>

// out[b,k] = (WHT_2048(concat(x1[b],x2[b]))[k])^2 / 2048
// (RZ phase is unit-modulus, input real -> |.|^2 removes it; 11 Hadamard
// stages = unnormalized WHT * 2^{-11/2}; after squaring -> 1/2048.)
//
// Stage plan (one smem exchange total):
//   layout A: j = t*16 + i     -> WHT16 in regs      (bits 0-3)
//   shfl_xor butterflies m=1,2,4 over lane bits      (bits 4-6)
//   smem exchange -> layout B: j = t + i*128
//   WHT16 in regs                                     (bits 7-10)

#define THREADS 128

// padded smem index: 4 pad floats per 32 floats (16B per 128B)
__device__ __forceinline__ int sidx(int j) { return j + ((j >> 5) << 2); }

__device__ __forceinline__ void wht16(float* v) {
#pragma unroll
    for (int m = 1; m < 16; m <<= 1) {
#pragma unroll
        for (int i = 0; i < 16; ++i) {
            if ((i & m) == 0) {
                float a = v[i];
                float b = v[i | m];
                v[i]     = a + b;
                v[i | m] = a - b;
            }
        }
    }
}

__global__ void __launch_bounds__(THREADS) qf_wht_kernel(
    const float* __restrict__ x1,
    const float* __restrict__ x2,
    float* __restrict__ out)
{
    __shared__ float buf[2048 + 64 * 4];  // 2304 floats (9216 B)

    const int t    = threadIdx.x;
    const int lane = t & 31;
    const int row  = blockIdx.x;

    float v[16];

    // ---- Load layout A: j = t*16 + i (float4, fully coalesced) ----
    const float* src = (t < 64)
        ? (x1 + (size_t)row * 1024 + (size_t)t * 16)
        : (x2 + (size_t)row * 1024 + (size_t)(t - 64) * 16);
    const float4* p4 = reinterpret_cast<const float4*>(src);
#pragma unroll
    for (int k = 0; k < 4; ++k) {
        float4 f = p4[k];
        v[4 * k + 0] = f.x;
        v[4 * k + 1] = f.y;
        v[4 * k + 2] = f.z;
        v[4 * k + 3] = f.w;
    }

    // ---- bits 0-3 in registers ----
    wht16(v);

    // ---- bits 4-6 via warp shuffles (lane bits 0-2) ----
#pragma unroll
    for (int m = 1; m < 8; m <<= 1) {
        const float s = (lane & m) ? -1.0f : 1.0f;
#pragma unroll
        for (int i = 0; i < 16; ++i) {
            float o = __shfl_xor_sync(0xffffffffu, v[i], m);
            v[i] = fmaf(s, v[i], o);   // lower lane: v+o ; upper lane: o-v
        }
    }

    // ---- single smem exchange: layout A -> layout B ----
    // write side: STS.128 x4, conflict-free under the 16B/128B padding
#pragma unroll
    for (int k = 0; k < 4; ++k) {
        int j0 = t * 16 + 4 * k;
        *reinterpret_cast<float4*>(&buf[sidx(j0)]) =
            make_float4(v[4 * k + 0], v[4 * k + 1], v[4 * k + 2], v[4 * k + 3]);
    }
    __syncthreads();

    // read side: layout B, j = t + i*128 (32 consecutive floats per warp-op)
#pragma unroll
    for (int i = 0; i < 16; ++i) {
        int j = t + (i << 7);
        v[i] = buf[sidx(j)];
    }

    // ---- bits 7-10 in registers ----
    wht16(v);

    // ---- epilogue: square, scale, coalesced store (128B per warp-op) ----
    const float scale = 1.0f / 2048.0f;
    float* orow = out + (size_t)row * 2048;
#pragma unroll
    for (int i = 0; i < 16; ++i) {
        int j = t + (i << 7);
        float f = v[i];
        orow[j] = f * f * scale;
    }
}

extern "C" void kernel_launch(void* const* d_in, const int* in_sizes, int n_in,
                              void* d_out, int out_size)
{
    const float* x1 = (const float*)d_in[0];
    const float* x2 = (const float*)d_in[1];
    float* out = (float*)d_out;
    (void)in_sizes; (void)n_in; (void)out_size;

    qf_wht_kernel<<<8192, THREADS>>>(x1, x2, out);
}

// round 3
// speedup vs baseline: 1.1405x; 1.0417x over previous
#include <cuda_runtime.h>

// out[b,k] = (WHT_2048(concat(x1[b],x2[b]))[k])^2 / 2048
// Two rows per thread packed into f32x2 (Blackwell packed fp32 via inline PTX).
// Three register layouts, two conflict-free smem exchanges, no shuffles.

#define THREADS 128
typedef unsigned long long u64;

__device__ __forceinline__ u64 pack2(float a, float b) {
    u64 d; asm("mov.b64 %0,{%1,%2};" : "=l"(d) : "f"(a), "f"(b)); return d;
}
__device__ __forceinline__ void unpack2(u64 v, float& a, float& b) {
    asm("mov.b64 {%0,%1},%2;" : "=f"(a), "=f"(b) : "l"(v));
}
__device__ __forceinline__ u64 add2(u64 a, u64 b) {
    u64 d; asm("add.rn.f32x2 %0,%1,%2;" : "=l"(d) : "l"(a), "l"(b)); return d;
}
__device__ __forceinline__ u64 fma2(u64 a, u64 b, u64 c) {
    u64 d; asm("fma.rn.f32x2 %0,%1,%2,%3;" : "=l"(d) : "l"(a), "l"(b), "l"(c)); return d;
}
__device__ __forceinline__ u64 mul2(u64 a, u64 b) {
    u64 d; asm("mul.rn.f32x2 %0,%1,%2;" : "=l"(d) : "l"(a), "l"(b)); return d;
}

// butterfly on packed pairs: (x,y) -> (x+y, x-y)
#define BFLY(x, y) do { u64 _s = add2(x, y); (y) = fma2(y, neg1, x); (x) = _s; } while (0)

// padded smem index in 8B elements: +2 elements per 16 (conflict-free phases)
__device__ __forceinline__ int sidx8(int j) { return j + ((j >> 4) << 1); }

__global__ void __launch_bounds__(THREADS) qf_wht_kernel(
    const float* __restrict__ x1,
    const float* __restrict__ x2,
    float* __restrict__ out)
{
    __shared__ __align__(16) u64 buf[2304];  // 2048 + 2*128 pad = 18432 B

    const int t = threadIdx.x;
    const u64 neg1 = 0xBF800000BF800000ULL;  // (-1.0f, -1.0f)

    const int rowA = blockIdx.x * 2;
    const int rowB = rowA + 1;

    u64 v[16];

    // ---- Load layout A: j = t*16 + i, two rows packed ----
    const size_t colbase = (size_t)((t < 64) ? t : (t - 64)) * 16;
    const float* baseA = (t < 64) ? (x1 + (size_t)rowA * 1024 + colbase)
                                  : (x2 + (size_t)rowA * 1024 + colbase);
    const float* baseB = (t < 64) ? (x1 + (size_t)rowB * 1024 + colbase)
                                  : (x2 + (size_t)rowB * 1024 + colbase);
#pragma unroll
    for (int k = 0; k < 4; ++k) {
        float4 fa = reinterpret_cast<const float4*>(baseA)[k];
        float4 fb = reinterpret_cast<const float4*>(baseB)[k];
        v[4 * k + 0] = pack2(fa.x, fb.x);
        v[4 * k + 1] = pack2(fa.y, fb.y);
        v[4 * k + 2] = pack2(fa.z, fb.z);
        v[4 * k + 3] = pack2(fa.w, fb.w);
    }

    // ---- bits 0-3: wht16 in registers ----
#pragma unroll
    for (int m = 1; m < 16; m <<= 1)
#pragma unroll
        for (int i = 0; i < 16; ++i)
            if ((i & m) == 0) BFLY(v[i], v[i | m]);

    // ---- exchange 1: layout A -> layout B (j = i*128 + t) ----
    // write: addr8 = sidx8(16t + 2k) = 18t + 2k, ulonglong2 (STS.128), conflict-free
#pragma unroll
    for (int k = 0; k < 8; ++k)
        *reinterpret_cast<ulonglong2*>(&buf[18 * t + 2 * k]) =
            make_ulonglong2(v[2 * k], v[2 * k + 1]);
    __syncthreads();

    const int tb = t + ((t >> 4) << 1);  // sidx8(t) for t<... within-row offset
#pragma unroll
    for (int i = 0; i < 16; ++i)
        v[i] = buf[144 * i + tb];        // sidx8(128i + t)

    // ---- bits 7-10: wht16 in registers ----
#pragma unroll
    for (int m = 1; m < 16; m <<= 1)
#pragma unroll
        for (int i = 0; i < 16; ++i)
            if ((i & m) == 0) BFLY(v[i], v[i | m]);

    // ---- exchange 2: write back to SAME addresses (no sync needed before write),
    //      then read layout C ----
#pragma unroll
    for (int i = 0; i < 16; ++i)
        buf[144 * i + tb] = v[i];
    __syncthreads();

    // layout C: j = (t&15) | ((i&7)<<4) | ((t>>4)<<7) | ((i>>3)<<10)
    const int base = (t & 15) | ((t >> 4) << 7);
#pragma unroll
    for (int i = 0; i < 16; ++i) {
        int j = base | ((i & 7) << 4) | ((i >> 3) << 10);
        v[i] = buf[sidx8(j)];
    }

    // ---- bits 4-6: wht8 on each half (bit 10 already done) ----
#pragma unroll
    for (int m = 1; m < 8; m <<= 1)
#pragma unroll
        for (int h = 0; h < 16; h += 8)
#pragma unroll
            for (int i = 0; i < 8; ++i)
                if ((i & m) == 0) BFLY(v[h + i], v[h + (i | m)]);

    // ---- epilogue: square * 1/2048, store both rows ----
    const u64 scale2 = 0x3A0000003A000000ULL;  // (1/2048, 1/2048)
    float* orowA = out + (size_t)rowA * 2048;
    float* orowB = out + (size_t)rowB * 2048;
#pragma unroll
    for (int i = 0; i < 16; ++i) {
        int j = base | ((i & 7) << 4) | ((i >> 3) << 10);
        u64 sq = mul2(mul2(v[i], v[i]), scale2);
        float fa, fb;
        unpack2(sq, fa, fb);
        orowA[j] = fa;
        orowB[j] = fb;
    }
}

extern "C" void kernel_launch(void* const* d_in, const int* in_sizes, int n_in,
                              void* d_out, int out_size)
{
    const float* x1 = (const float*)d_in[0];
    const float* x2 = (const float*)d_in[1];
    float* out = (float*)d_out;
    (void)in_sizes; (void)n_in; (void)out_size;

    qf_wht_kernel<<<4096, THREADS>>>(x1, x2, out);
}

// round 6
// speedup vs baseline: 1.3511x; 1.1847x over previous
#include <cuda_runtime.h>

// out[b,k] = (WHT_2048(concat(x1[b],x2[b]))[k])^2 / 2048
// Two rows per thread packed as f32x2. Three layouts / two smem exchanges,
// XOR-swizzled smem (conflict-free, no padding), fully coalesced LDG/STG.
//
//  layout A: j = k*512 + 4t + c   (local bits 0,1,9,10)  <- coalesced float4 loads
//  layout B: j = (i<<2)|(t&3)|((t>>2)<<6)      (local bits 2..5)
//  layout C: j = (i&1)|((t&31)<<1)|((i>>1)<<6)|((t>>5)<<9) (local bits 6..8)
//  smem addr swizzle: a = j ^ ((j>>4)&15)

#define THREADS 128
typedef unsigned long long u64;

__device__ __forceinline__ u64 pack2(float a, float b) {
    u64 d; asm("mov.b64 %0,{%1,%2};" : "=l"(d) : "f"(a), "f"(b)); return d;
}
__device__ __forceinline__ void unpack2(u64 v, float& a, float& b) {
    asm("mov.b64 {%0,%1},%2;" : "=f"(a), "=f"(b) : "l"(v));
}
__device__ __forceinline__ u64 add2(u64 a, u64 b) {
    u64 d; asm("add.rn.f32x2 %0,%1,%2;" : "=l"(d) : "l"(a), "l"(b)); return d;
}
__device__ __forceinline__ u64 fma2(u64 a, u64 b, u64 c) {
    u64 d; asm("fma.rn.f32x2 %0,%1,%2,%3;" : "=l"(d) : "l"(a), "l"(b), "l"(c)); return d;
}
__device__ __forceinline__ u64 mul2(u64 a, u64 b) {
    u64 d; asm("mul.rn.f32x2 %0,%1,%2;" : "=l"(d) : "l"(a), "l"(b)); return d;
}

#define BFLY(x, y) do { u64 _s = add2(x, y); (y) = fma2(y, neg1, x); (x) = _s; } while (0)

__device__ __forceinline__ int swz(int j) { return j ^ ((j >> 4) & 15); }

__device__ __forceinline__ void wht16(u64* v, const u64 neg1) {
#pragma unroll
    for (int m = 1; m < 16; m <<= 1)
#pragma unroll
        for (int i = 0; i < 16; ++i)
            if ((i & m) == 0) BFLY(v[i], v[i | m]);
}

__global__ void __launch_bounds__(THREADS) qf_wht_kernel(
    const float* __restrict__ x1,
    const float* __restrict__ x2,
    float* __restrict__ out)
{
    __shared__ __align__(16) u64 buf[2048];   // 16 KB, swizzled, no padding

    const int t = threadIdx.x;
    const u64 neg1 = 0xBF800000BF800000ULL;   // (-1.0f, -1.0f)

    const int rowA = blockIdx.x * 2;
    const int rowB = rowA + 1;

    u64 v[16];

    // ---- coalesced load, layout A: v[k*4+c] = col (k*512 + 4t + c) ----
#pragma unroll
    for (int k = 0; k < 4; ++k) {
        const int col = k * 512 + 4 * t;      // uniform per k: k<2 -> x1, k>=2 -> x2
        const float* pa;
        const float* pb;
        if (k < 2) {
            pa = x1 + (size_t)rowA * 1024 + col;
            pb = x1 + (size_t)rowB * 1024 + col;
        } else {
            pa = x2 + (size_t)rowA * 1024 + (col - 1024);
            pb = x2 + (size_t)rowB * 1024 + (col - 1024);
        }
        float4 fa = *reinterpret_cast<const float4*>(pa);
        float4 fb = *reinterpret_cast<const float4*>(pb);
        v[k * 4 + 0] = pack2(fa.x, fb.x);
        v[k * 4 + 1] = pack2(fa.y, fb.y);
        v[k * 4 + 2] = pack2(fa.z, fb.z);
        v[k * 4 + 3] = pack2(fa.w, fb.w);
    }

    // ---- phase 1: bits 0,1 (c) and 9,10 (k) -> plain wht16 on index (k<<2|c) ----
    wht16(v, neg1);

    // ---- exchange 1: write layout A ----
#pragma unroll
    for (int k = 0; k < 4; ++k)
#pragma unroll
        for (int c = 0; c < 4; ++c)
            buf[swz(k * 512 + 4 * t + c)] = v[k * 4 + c];
    __syncthreads();

    // ---- read layout B: j = (i<<2) | (t&3) | ((t>>2)<<6) ----
    const int tb = (t & 3) | ((t >> 2) << 6);
#pragma unroll
    for (int i = 0; i < 16; ++i)
        v[i] = buf[swz((i << 2) | tb)];

    // ---- phase 2: bits 2..5 ----
    wht16(v, neg1);

    // ---- exchange 2: write back to the SAME addresses (own elements) ----
#pragma unroll
    for (int i = 0; i < 16; ++i)
        buf[swz((i << 2) | tb)] = v[i];
    __syncthreads();

    // ---- read layout C: j = (i&1) | ((t&31)<<1) | ((i>>1)<<6) | ((t>>5)<<9) ----
    const int tc = ((t & 31) << 1) | ((t >> 5) << 9);
#pragma unroll
    for (int i = 0; i < 16; ++i)
        v[i] = buf[swz(tc | (i & 1) | ((i >> 1) << 6))];

    // ---- phase 3: bits 6..8 (WHT8 over q=i>>1, two copies h=i&1) ----
#pragma unroll
    for (int m = 1; m < 8; m <<= 1)
#pragma unroll
        for (int h = 0; h < 2; ++h)
#pragma unroll
            for (int q = 0; q < 8; ++q)
                if ((q & m) == 0) BFLY(v[q * 2 + h], v[(q | m) * 2 + h]);

    // ---- epilogue: square * 1/2048, coalesced float2 stores ----
    const u64 scale2 = 0x3A0000003A000000ULL;  // (1/2048, 1/2048)
    float* oA = out + (size_t)rowA * 2048;
    float* oB = out + (size_t)rowB * 2048;
#pragma unroll
    for (int p = 0; p < 8; ++p) {
        const int j0 = tc | (p << 6);          // bit 0 = 0, even -> 8B aligned
        u64 s0 = mul2(mul2(v[2 * p],     v[2 * p]),     scale2);  // col j0
        u64 s1 = mul2(mul2(v[2 * p + 1], v[2 * p + 1]), scale2);  // col j0+1
        float a0, b0, a1, b1;
        unpack2(s0, a0, b0);
        unpack2(s1, a1, b1);
        *reinterpret_cast<float2*>(oA + j0) = make_float2(a0, a1);
        *reinterpret_cast<float2*>(oB + j0) = make_float2(b0, b1);
    }
}

extern "C" void kernel_launch(void* const* d_in, const int* in_sizes, int n_in,
                              void* d_out, int out_size)
{
    const float* x1 = (const float*)d_in[0];
    const float* x2 = (const float*)d_in[1];
    float* out = (float*)d_out;
    (void)in_sizes; (void)n_in; (void)out_size;

    qf_wht_kernel<<<4096, THREADS>>>(x1, x2, out);
}